// round 5
// baseline (speedup 1.0000x reference)
#include <cuda_runtime.h>
#include <math.h>

#define TTOK  16384
#define HID   768
#define NHEAD 12
#define HDIM  64
#define SEQL  2048
#define NSEQ  8

// Scratch (allocation-free rule: __device__ globals)
__device__ float g_xn [TTOK * HID];
__device__ float g_q  [TTOK * HID];
__device__ float g_k  [TTOK * HID];
__device__ float g_v  [TTOK * HID];
__device__ float g_att[TTOK * HID];

// ---------------------------------------------------------------------------
// Helpers: tf32 round-to-nearest conversion + m16n8k8 tf32 MMA
// ---------------------------------------------------------------------------
__device__ __forceinline__ float f2tf(float x) {
    unsigned r;
    asm("cvt.rna.tf32.f32 %0, %1;" : "=r"(r) : "f"(x));
    return __uint_as_float(r);
}

__device__ __forceinline__ void mma_tf32(float* c, const unsigned* a, const unsigned* b) {
    asm volatile(
        "mma.sync.aligned.m16n8k8.row.col.f32.tf32.tf32.f32 "
        "{%0,%1,%2,%3}, {%4,%5,%6,%7}, {%8,%9}, {%0,%1,%2,%3};\n"
        : "+f"(c[0]), "+f"(c[1]), "+f"(c[2]), "+f"(c[3])
        : "r"(a[0]), "r"(a[1]), "r"(a[2]), "r"(a[3]),
          "r"(b[0]), "r"(b[1]));
}

// ---------------------------------------------------------------------------
// LayerNorm: one block per row (768 cols), 256 threads, 3 elems/thread
// ---------------------------------------------------------------------------
__global__ __launch_bounds__(256) void ln_kernel(
    const float* __restrict__ x, const float* __restrict__ w,
    const float* __restrict__ b, float* __restrict__ xn)
{
    int row = blockIdx.x;
    int tid = threadIdx.x;
    const float* xr = x + (size_t)row * HID;

    float v0 = xr[tid], v1 = xr[tid + 256], v2 = xr[tid + 512];
    float s  = v0 + v1 + v2;
    float ss = v0 * v0 + v1 * v1 + v2 * v2;

    #pragma unroll
    for (int o = 16; o > 0; o >>= 1) {
        s  += __shfl_xor_sync(0xffffffffu, s,  o);
        ss += __shfl_xor_sync(0xffffffffu, ss, o);
    }
    __shared__ float sm[8], sm2[8];
    if ((tid & 31) == 0) { sm[tid >> 5] = s; sm2[tid >> 5] = ss; }
    __syncthreads();
    float ts = 0.f, tss = 0.f;
    #pragma unroll
    for (int i = 0; i < 8; i++) { ts += sm[i]; tss += sm2[i]; }

    float mean = ts * (1.0f / HID);
    float var  = tss * (1.0f / HID) - mean * mean;
    float inv  = rsqrtf(var + 1e-12f);

    float* xo = xn + (size_t)row * HID;
    xo[tid      ] = (v0 - mean) * inv * w[tid      ] + b[tid      ];
    xo[tid + 256] = (v1 - mean) * inv * w[tid + 256] + b[tid + 256];
    xo[tid + 512] = (v2 - mean) * inv * w[tid + 512] + b[tid + 512];
}

// ---------------------------------------------------------------------------
// TF32 tensor-core GEMM: C[M,768] = A[M,768] @ B[768,768] + bias (+ addsrc)
// 128x128 block tile, BK=16, 256 threads = 8 warps (2x4), warp tile 64x32.
// Double-buffered smem, one barrier per K-chunk.
// ---------------------------------------------------------------------------
#define GLDA 20
#define GLDB 132

__global__ __launch_bounds__(256) void gemm_kernel(
    const float* __restrict__ A, const float* __restrict__ B,
    const float* __restrict__ bias, const float* __restrict__ addsrc,
    float* __restrict__ C)
{
    const int K = HID, N = HID;
    __shared__ float As[2][128 * GLDA];
    __shared__ float Bs[2][16 * GLDB];

    int tid = threadIdx.x;
    int w = tid >> 5, lane = tid & 31;
    int g = lane >> 2, q = lane & 3;
    int warpRow = w >> 2;          // 0..1
    int warpCol = w & 3;           // 0..3
    int mBase = warpRow * 64;
    int nBase = warpCol * 32;

    int bx = blockIdx.x, by = blockIdx.y;

    // gmem load mapping
    int aRow = tid >> 1;                 // 0..127
    int aK0  = (tid & 1) * 8;            // 0 or 8
    int bRow = tid >> 4;                 // 0..15
    int bC0  = (tid & 15) * 8;           // 0..120
    const float* aG = A + (size_t)(by * 128 + aRow) * K + aK0;
    const float* bG = B + (size_t)bRow * N + bx * 128 + bC0;

    float acc[4][4][4];
    #pragma unroll
    for (int mt = 0; mt < 4; mt++)
        #pragma unroll
        for (int nt = 0; nt < 4; nt++)
            #pragma unroll
            for (int i = 0; i < 4; i++) acc[mt][nt][i] = 0.f;

    // preload chunk 0
    float4 pa0 = *(const float4*)(aG);
    float4 pa1 = *(const float4*)(aG + 4);
    float4 pb0 = *(const float4*)(bG);
    float4 pb1 = *(const float4*)(bG + 4);
    {
        float* as = &As[0][aRow * GLDA + aK0];
        as[0] = f2tf(pa0.x); as[1] = f2tf(pa0.y); as[2] = f2tf(pa0.z); as[3] = f2tf(pa0.w);
        as[4] = f2tf(pa1.x); as[5] = f2tf(pa1.y); as[6] = f2tf(pa1.z); as[7] = f2tf(pa1.w);
        float* bs = &Bs[0][bRow * GLDB + bC0];
        bs[0] = f2tf(pb0.x); bs[1] = f2tf(pb0.y); bs[2] = f2tf(pb0.z); bs[3] = f2tf(pb0.w);
        bs[4] = f2tf(pb1.x); bs[5] = f2tf(pb1.y); bs[6] = f2tf(pb1.z); bs[7] = f2tf(pb1.w);
    }
    __syncthreads();

    const int NCHUNK = K / 16;  // 48
    for (int c = 0; c < NCHUNK; c++) {
        int cur = c & 1;
        if (c + 1 < NCHUNK) {
            int k0 = (c + 1) * 16;
            pa0 = *(const float4*)(aG + k0);
            pa1 = *(const float4*)(aG + k0 + 4);
            pb0 = *(const float4*)(bG + (size_t)k0 * N);
            pb1 = *(const float4*)(bG + (size_t)k0 * N + 4);
        }

        #pragma unroll
        for (int ks = 0; ks < 2; ks++) {
            int k0 = ks * 8;
            unsigned af[4][4];
            #pragma unroll
            for (int mt = 0; mt < 4; mt++) {
                const float* ap = &As[cur][(mBase + mt * 16 + g) * GLDA + k0 + q];
                af[mt][0] = __float_as_uint(ap[0]);
                af[mt][1] = __float_as_uint(ap[8 * GLDA]);
                af[mt][2] = __float_as_uint(ap[4]);
                af[mt][3] = __float_as_uint(ap[8 * GLDA + 4]);
            }
            unsigned bf[4][2];
            #pragma unroll
            for (int nt = 0; nt < 4; nt++) {
                const float* bp = &Bs[cur][(k0 + q) * GLDB + nBase + nt * 8 + g];
                bf[nt][0] = __float_as_uint(bp[0]);
                bf[nt][1] = __float_as_uint(bp[4 * GLDB]);
            }
            #pragma unroll
            for (int mt = 0; mt < 4; mt++)
                #pragma unroll
                for (int nt = 0; nt < 4; nt++)
                    mma_tf32(acc[mt][nt], af[mt], bf[nt]);
        }

        if (c + 1 < NCHUNK) {
            int nxt = (c + 1) & 1;
            float* as = &As[nxt][aRow * GLDA + aK0];
            as[0] = f2tf(pa0.x); as[1] = f2tf(pa0.y); as[2] = f2tf(pa0.z); as[3] = f2tf(pa0.w);
            as[4] = f2tf(pa1.x); as[5] = f2tf(pa1.y); as[6] = f2tf(pa1.z); as[7] = f2tf(pa1.w);
            float* bs = &Bs[nxt][bRow * GLDB + bC0];
            bs[0] = f2tf(pb0.x); bs[1] = f2tf(pb0.y); bs[2] = f2tf(pb0.z); bs[3] = f2tf(pb0.w);
            bs[4] = f2tf(pb1.x); bs[5] = f2tf(pb1.y); bs[6] = f2tf(pb1.z); bs[7] = f2tf(pb1.w);
        }
        __syncthreads();
    }

    // Epilogue
    #pragma unroll
    for (int mt = 0; mt < 4; mt++) {
        #pragma unroll
        for (int half = 0; half < 2; half++) {
            size_t row = (size_t)by * 128 + mBase + mt * 16 + g + half * 8;
            #pragma unroll
            for (int nt = 0; nt < 4; nt++) {
                int col = bx * 128 + nBase + nt * 8 + 2 * q;
                float2 o;
                o.x = acc[mt][nt][half * 2 + 0] + bias[col];
                o.y = acc[mt][nt][half * 2 + 1] + bias[col + 1];
                if (addsrc) {
                    const float2 r = *(const float2*)(addsrc + row * N + col);
                    o.x += r.x; o.y += r.y;
                }
                *(float2*)(C + row * N + col) = o;
            }
        }
    }
}

// ---------------------------------------------------------------------------
// RoPE (in place on q and k). pos = token % 2048. Half-split convention.
// ---------------------------------------------------------------------------
__global__ __launch_bounds__(NHEAD * 32) void rope_kernel(
    float* __restrict__ q, float* __restrict__ k)
{
    int t = blockIdx.x;
    int h = threadIdx.x >> 5;
    int i = threadIdx.x & 31;
    int pos = t & (SEQL - 1);

    float invf  = powf(10000.0f, -((float)(2 * i) / (float)HDIM));
    float theta = (float)pos * invf;
    float sn, cs;
    sincosf(theta, &sn, &cs);

    size_t base = (size_t)t * HID + h * HDIM;
    float x1 = q[base + i], x2 = q[base + 32 + i];
    q[base + i]      = x1 * cs - x2 * sn;
    q[base + 32 + i] = x2 * cs + x1 * sn;
    x1 = k[base + i]; x2 = k[base + 32 + i];
    k[base + i]      = x1 * cs - x2 * sn;
    k[base + 32 + i] = x2 * cs + x1 * sn;
}

// ---------------------------------------------------------------------------
// Flash attention (FA2 style) on TF32 tensor cores.
// Block = (seq, head, 64-row q-tile); 128 threads = 4 warps x 16 rows.
// smem: Qs[64][68] (persistent, pre-scaled by 1/8), Ks[64][68] (reused as P),
//       Vt[64][68] (V transposed). 52224 B dynamic.
// ---------------------------------------------------------------------------
#define LDA 68

__global__ __launch_bounds__(128) void attn_kernel(
    const float* __restrict__ Q, const float* __restrict__ Kg,
    const float* __restrict__ Vg, float* __restrict__ O)
{
    extern __shared__ float smx[];
    float* Qs = smx;                 // [64][LDA]
    float* Ks = smx + 64 * LDA;      // K tile, later P tile
    float* Vt = smx + 2 * 64 * LDA;  // [d][j]

    int qt = blockIdx.x, h = blockIdx.y, sq = blockIdx.z;
    int tid = threadIdx.x;
    int w = tid >> 5, lane = tid & 31;
    int g = lane >> 2, q = lane & 3;
    int rBase = w * 16;
    const size_t seqBase = (size_t)sq * SEQL;

    int lrow = tid >> 1;           // 0..63
    int dh   = (tid & 1) * 32;     // 0 or 32

    // Load Q tile (pre-scaled by softmax scale 1/8, tf32-rounded)
    {
        const float* qp = Q + (seqBase + (size_t)qt * 64 + lrow) * HID + h * HDIM + dh;
        #pragma unroll
        for (int u = 0; u < 8; u++) {
            float4 v = *(const float4*)(qp + 4 * u);
            float* dst = &Qs[lrow * LDA + dh + 4 * u];
            dst[0] = f2tf(v.x * 0.125f);
            dst[1] = f2tf(v.y * 0.125f);
            dst[2] = f2tf(v.z * 0.125f);
            dst[3] = f2tf(v.w * 0.125f);
        }
    }

    float oAcc[8][4];
    #pragma unroll
    for (int nt = 0; nt < 8; nt++)
        #pragma unroll
        for (int i = 0; i < 4; i++) oAcc[nt][i] = 0.f;
    float m1 = -1e30f, m2 = -1e30f, l1 = 0.f, l2 = 0.f;

    for (int kt = 0; kt < SEQL / 64; kt++) {
        __syncthreads();  // prev PV done reading Ks(P)/Vt; Q visible (iter 0)

        // Load K tile (rows j x d) and V tile transposed (d x j)
        {
            const float* kp = Kg + (seqBase + (size_t)kt * 64 + lrow) * HID + h * HDIM + dh;
            const float* vp = Vg + (seqBase + (size_t)kt * 64 + lrow) * HID + h * HDIM + dh;
            #pragma unroll
            for (int u = 0; u < 8; u++) {
                float4 kv = *(const float4*)(kp + 4 * u);
                float* kd = &Ks[lrow * LDA + dh + 4 * u];
                kd[0] = f2tf(kv.x); kd[1] = f2tf(kv.y);
                kd[2] = f2tf(kv.z); kd[3] = f2tf(kv.w);
                float4 vv = *(const float4*)(vp + 4 * u);
                int d0 = dh + 4 * u;
                Vt[(d0 + 0) * LDA + lrow] = f2tf(vv.x);
                Vt[(d0 + 1) * LDA + lrow] = f2tf(vv.y);
                Vt[(d0 + 2) * LDA + lrow] = f2tf(vv.z);
                Vt[(d0 + 3) * LDA + lrow] = f2tf(vv.w);
            }
        }
        __syncthreads();

        // S = Q K^T  (warp: 16 rows x 64 cols, 8 n-tiles)
        float sAcc[8][4];
        #pragma unroll
        for (int nt = 0; nt < 8; nt++)
            #pragma unroll
            for (int i = 0; i < 4; i++) sAcc[nt][i] = 0.f;

        #pragma unroll
        for (int s = 0; s < 8; s++) {
            int k0 = s * 8;
            unsigned af[4];
            const float* ap = &Qs[(rBase + g) * LDA + k0 + q];
            af[0] = __float_as_uint(ap[0]);
            af[1] = __float_as_uint(ap[8 * LDA]);
            af[2] = __float_as_uint(ap[4]);
            af[3] = __float_as_uint(ap[8 * LDA + 4]);
            #pragma unroll
            for (int nt = 0; nt < 8; nt++) {
                unsigned bf[2];
                const float* bp = &Ks[(nt * 8 + g) * LDA + k0 + q];
                bf[0] = __float_as_uint(bp[0]);
                bf[1] = __float_as_uint(bp[4]);
                mma_tf32(sAcc[nt], af, bf);
            }
        }

        // Online softmax (rows rBase+g and rBase+g+8; quad shuffles)
        float rmax1 = -1e30f, rmax2 = -1e30f;
        #pragma unroll
        for (int nt = 0; nt < 8; nt++) {
            rmax1 = fmaxf(rmax1, fmaxf(sAcc[nt][0], sAcc[nt][1]));
            rmax2 = fmaxf(rmax2, fmaxf(sAcc[nt][2], sAcc[nt][3]));
        }
        rmax1 = fmaxf(rmax1, __shfl_xor_sync(0xffffffffu, rmax1, 1));
        rmax1 = fmaxf(rmax1, __shfl_xor_sync(0xffffffffu, rmax1, 2));
        rmax2 = fmaxf(rmax2, __shfl_xor_sync(0xffffffffu, rmax2, 1));
        rmax2 = fmaxf(rmax2, __shfl_xor_sync(0xffffffffu, rmax2, 2));

        float mn1 = fmaxf(m1, rmax1), mn2 = fmaxf(m2, rmax2);
        float alpha1 = __expf(m1 - mn1), alpha2 = __expf(m2 - mn2);
        m1 = mn1; m2 = mn2;

        float rsum1 = 0.f, rsum2 = 0.f;
        #pragma unroll
        for (int nt = 0; nt < 8; nt++) {
            sAcc[nt][0] = __expf(sAcc[nt][0] - m1);
            sAcc[nt][1] = __expf(sAcc[nt][1] - m1);
            sAcc[nt][2] = __expf(sAcc[nt][2] - m2);
            sAcc[nt][3] = __expf(sAcc[nt][3] - m2);
            rsum1 += sAcc[nt][0] + sAcc[nt][1];
            rsum2 += sAcc[nt][2] + sAcc[nt][3];
        }
        rsum1 += __shfl_xor_sync(0xffffffffu, rsum1, 1);
        rsum1 += __shfl_xor_sync(0xffffffffu, rsum1, 2);
        rsum2 += __shfl_xor_sync(0xffffffffu, rsum2, 1);
        rsum2 += __shfl_xor_sync(0xffffffffu, rsum2, 2);
        l1 = l1 * alpha1 + rsum1;
        l2 = l2 * alpha2 + rsum2;

        #pragma unroll
        for (int nt = 0; nt < 8; nt++) {
            oAcc[nt][0] *= alpha1; oAcc[nt][1] *= alpha1;
            oAcc[nt][2] *= alpha2; oAcc[nt][3] *= alpha2;
        }

        __syncthreads();  // all warps done reading Ks as K

        // Write P (tf32) into Ks region; warp-private rows
        #pragma unroll
        for (int nt = 0; nt < 8; nt++) {
            int c = nt * 8 + 2 * q;
            Ks[(rBase + g) * LDA + c]         = f2tf(sAcc[nt][0]);
            Ks[(rBase + g) * LDA + c + 1]     = f2tf(sAcc[nt][1]);
            Ks[(rBase + g + 8) * LDA + c]     = f2tf(sAcc[nt][2]);
            Ks[(rBase + g + 8) * LDA + c + 1] = f2tf(sAcc[nt][3]);
        }
        __syncwarp();

        // O += P V
        #pragma unroll
        for (int s = 0; s < 8; s++) {
            int k0 = s * 8;
            unsigned af[4];
            const float* ap = &Ks[(rBase + g) * LDA + k0 + q];
            af[0] = __float_as_uint(ap[0]);
            af[1] = __float_as_uint(ap[8 * LDA]);
            af[2] = __float_as_uint(ap[4]);
            af[3] = __float_as_uint(ap[8 * LDA + 4]);
            #pragma unroll
            for (int nt = 0; nt < 8; nt++) {
                unsigned bf[2];
                const float* bp = &Vt[(nt * 8 + g) * LDA + k0 + q];
                bf[0] = __float_as_uint(bp[0]);
                bf[1] = __float_as_uint(bp[4]);
                mma_tf32(oAcc[nt], af, bf);
            }
        }
    }

    // Epilogue
    float inv1 = 1.0f / l1, inv2 = 1.0f / l2;
    size_t row1 = seqBase + (size_t)qt * 64 + rBase + g;
    size_t row2 = row1 + 8;
    #pragma unroll
    for (int nt = 0; nt < 8; nt++) {
        int col = h * HDIM + nt * 8 + 2 * q;
        float2 o1 = make_float2(oAcc[nt][0] * inv1, oAcc[nt][1] * inv1);
        float2 o2 = make_float2(oAcc[nt][2] * inv2, oAcc[nt][3] * inv2);
        *(float2*)(O + row1 * HID + col) = o1;
        *(float2*)(O + row2 * HID + col) = o2;
    }
}

// ---------------------------------------------------------------------------
extern "C" void kernel_launch(void* const* d_in, const int* in_sizes, int n_in,
                              void* d_out, int out_size)
{
    (void)in_sizes; (void)n_in; (void)out_size;
    const float* hs = (const float*)d_in[0];
    const float* nw = (const float*)d_in[3];
    const float* nb = (const float*)d_in[4];
    const float* Wq = (const float*)d_in[5];
    const float* bq = (const float*)d_in[6];
    const float* Wk = (const float*)d_in[7];
    const float* bk = (const float*)d_in[8];
    const float* Wv = (const float*)d_in[9];
    const float* bv = (const float*)d_in[10];
    const float* Wo = (const float*)d_in[11];
    const float* bo = (const float*)d_in[12];
    float* out = (float*)d_out;

    float *xn, *q, *k, *v, *att;
    cudaGetSymbolAddress((void**)&xn,  g_xn);
    cudaGetSymbolAddress((void**)&q,   g_q);
    cudaGetSymbolAddress((void**)&k,   g_k);
    cudaGetSymbolAddress((void**)&v,   g_v);
    cudaGetSymbolAddress((void**)&att, g_att);

    const int ATTN_SMEM = 3 * 64 * LDA * sizeof(float);  // 52224
    static int attr_done = 0;
    if (!attr_done) {
        cudaFuncSetAttribute(attn_kernel,
                             cudaFuncAttributeMaxDynamicSharedMemorySize, ATTN_SMEM);
        attr_done = 1;
    }

    ln_kernel<<<TTOK, 256>>>(hs, nw, nb, xn);

    dim3 ggrid(HID / 128, TTOK / 128);
    gemm_kernel<<<ggrid, 256>>>(xn, Wq, bq, nullptr, q);
    gemm_kernel<<<ggrid, 256>>>(xn, Wk, bk, nullptr, k);
    gemm_kernel<<<ggrid, 256>>>(xn, Wv, bv, nullptr, v);

    rope_kernel<<<TTOK, NHEAD * 32>>>(q, k);

    dim3 agrid(SEQL / 64, NHEAD, NSEQ);
    attn_kernel<<<agrid, 128, ATTN_SMEM>>>(q, k, v, att);

    gemm_kernel<<<ggrid, 256>>>(att, Wo, bo, xn, out);
}

// round 11
// speedup vs baseline: 3.2021x; 3.2021x over previous
#include <cuda_runtime.h>
#include <cuda_fp16.h>
#include <stdint.h>
#include <cstdint>
#include <math.h>

#define TTOK  16384
#define HID   768
#define NHEAD 12
#define HDIM  64
#define SEQL  2048
#define NSEQ  8

__device__ float  g_xn [TTOK * HID];
__device__ __half g_xh [TTOK * HID];
__device__ __half g_q  [TTOK * HID];
__device__ __half g_k  [TTOK * HID];
__device__ __half g_v  [TTOK * HID];
__device__ __half g_att[TTOK * HID];
__device__ __half g_Wh [4][HID * HID];

__device__ __forceinline__ void ldsm4(unsigned a, unsigned &r0, unsigned &r1,
                                      unsigned &r2, unsigned &r3) {
    asm volatile("ldmatrix.sync.aligned.m8n8.x4.shared.b16 {%0,%1,%2,%3}, [%4];"
        : "=r"(r0), "=r"(r1), "=r"(r2), "=r"(r3) : "r"(a));
}
__device__ __forceinline__ void ldsm4t(unsigned a, unsigned &r0, unsigned &r1,
                                       unsigned &r2, unsigned &r3) {
    asm volatile("ldmatrix.sync.aligned.m8n8.x4.trans.shared.b16 {%0,%1,%2,%3}, [%4];"
        : "=r"(r0), "=r"(r1), "=r"(r2), "=r"(r3) : "r"(a));
}
__device__ __forceinline__ void mma16816(float* c, const unsigned* a,
                                         unsigned b0, unsigned b1) {
    asm volatile(
        "mma.sync.aligned.m16n8k16.row.col.f32.f16.f16.f32 "
        "{%0,%1,%2,%3},{%4,%5,%6,%7},{%8,%9},{%0,%1,%2,%3};"
        : "+f"(c[0]), "+f"(c[1]), "+f"(c[2]), "+f"(c[3])
        : "r"(a[0]), "r"(a[1]), "r"(a[2]), "r"(a[3]), "r"(b0), "r"(b1));
}
__device__ __forceinline__ void cpa16(unsigned d, const void* s) {
    asm volatile("cp.async.ca.shared.global [%0], [%1], 16;" :: "r"(d), "l"(s));
}
#define CP_COMMIT  asm volatile("cp.async.commit_group;")
#define CP_WAIT0   asm volatile("cp.async.wait_group 0;")
#define CP_WAIT1   asm volatile("cp.async.wait_group 1;")

__device__ __forceinline__ unsigned f22h(float x, float y) {
    __half2 h = __floats2half2_rn(x, y);
    return *reinterpret_cast<unsigned*>(&h);
}

// ---- weight fp32->fp16, once ----
__global__ __launch_bounds__(256) void w2h_kernel(
    const float* __restrict__ a, const float* __restrict__ b,
    const float* __restrict__ c, const float* __restrict__ d)
{
    int i = blockIdx.x * 256 + threadIdx.x;
    g_Wh[0][i] = __float2half_rn(a[i]);
    g_Wh[1][i] = __float2half_rn(b[i]);
    g_Wh[2][i] = __float2half_rn(c[i]);
    g_Wh[3][i] = __float2half_rn(d[i]);
}

// ---- LayerNorm: fp32 out (residual) + fp16 out (GEMM A) ----
__global__ __launch_bounds__(256) void ln_kernel(
    const float* __restrict__ x, const float* __restrict__ w,
    const float* __restrict__ b, float* __restrict__ xn, __half* __restrict__ xh)
{
    int row = blockIdx.x, tid = threadIdx.x;
    const float* xr = x + (size_t)row * HID;
    float v0 = xr[tid], v1 = xr[tid + 256], v2 = xr[tid + 512];
    float s = v0 + v1 + v2, ss = v0 * v0 + v1 * v1 + v2 * v2;
    #pragma unroll
    for (int o = 16; o > 0; o >>= 1) {
        s  += __shfl_xor_sync(0xffffffffu, s,  o);
        ss += __shfl_xor_sync(0xffffffffu, ss, o);
    }
    __shared__ float sm[8], sm2[8];
    if ((tid & 31) == 0) { sm[tid >> 5] = s; sm2[tid >> 5] = ss; }
    __syncthreads();
    float ts = 0.f, tss = 0.f;
    #pragma unroll
    for (int i = 0; i < 8; i++) { ts += sm[i]; tss += sm2[i]; }
    float mean = ts * (1.0f / HID);
    float var  = tss * (1.0f / HID) - mean * mean;
    float inv  = rsqrtf(var + 1e-12f);
    float* xo = xn + (size_t)row * HID;
    __half* xo2 = xh + (size_t)row * HID;
    float o0 = (v0 - mean) * inv * w[tid      ] + b[tid      ];
    float o1 = (v1 - mean) * inv * w[tid + 256] + b[tid + 256];
    float o2 = (v2 - mean) * inv * w[tid + 512] + b[tid + 512];
    xo[tid] = o0; xo[tid + 256] = o1; xo[tid + 512] = o2;
    xo2[tid] = __float2half_rn(o0);
    xo2[tid + 256] = __float2half_rn(o1);
    xo2[tid + 512] = __float2half_rn(o2);
}

// ---- fp16 GEMM: 128x128 tile, BK=32, 8 warps, warp 64x32, cp.async x2 ----
#define AS_LD 40
#define BS_LD 136

template<bool HALF_OUT>
__global__ __launch_bounds__(256) void gemm_kernel(
    const __half* __restrict__ A, const __half* __restrict__ B,
    const float* __restrict__ bias, const float* __restrict__ addsrc,
    void* __restrict__ Cout)
{
    __shared__ __align__(16) __half As[2][128 * AS_LD];
    __shared__ __align__(16) __half Bs[2][32 * BS_LD];

    int tid = threadIdx.x, w = tid >> 5, lane = tid & 31;
    int g = lane >> 2, qd = lane & 3;
    int mBase = (w >> 2) * 64, nBase = (w & 3) * 32;
    int bx = blockIdx.x, by = blockIdx.y;
    int i8 = lane & 7, sel = lane >> 3;
    int rowOff = i8 + (sel & 1) * 8;
    int colOff = (sel & 2) ? 8 : 0;

    int aRow = tid >> 1, aSeg = (tid & 1) * 16;
    int bK = tid >> 3, bSeg = (tid & 7) * 16;
    const __half* aG = A + (size_t)(by * 128 + aRow) * HID + aSeg;
    const __half* bG = B + (size_t)bK * HID + bx * 128 + bSeg;

    unsigned sA = (unsigned)__cvta_generic_to_shared(&As[0][0]);
    unsigned sB = (unsigned)__cvta_generic_to_shared(&Bs[0][0]);
    const unsigned bufA = 128 * AS_LD * 2, bufB = 32 * BS_LD * 2;
    unsigned dA = sA + (aRow * AS_LD + aSeg) * 2;
    unsigned dB = sB + (bK * BS_LD + bSeg) * 2;

    float acc[4][4][4];
    #pragma unroll
    for (int mt = 0; mt < 4; mt++)
        #pragma unroll
        for (int nt = 0; nt < 4; nt++)
            #pragma unroll
            for (int i = 0; i < 4; i++) acc[mt][nt][i] = 0.f;

    cpa16(dA, aG); cpa16(dA + 16, aG + 8);
    cpa16(dB, bG); cpa16(dB + 16, bG + 8);
    CP_COMMIT;

    const int NI = HID / 32;
    for (int c = 0; c < NI; c++) {
        int cur = c & 1, nxt = cur ^ 1;
        if (c + 1 < NI) {
            int k0 = (c + 1) * 32;
            cpa16(dA + nxt * bufA, aG + k0);
            cpa16(dA + nxt * bufA + 16, aG + k0 + 8);
            cpa16(dB + nxt * bufB, bG + (size_t)k0 * HID);
            cpa16(dB + nxt * bufB + 16, bG + (size_t)k0 * HID + 8);
            CP_COMMIT; CP_WAIT1;
        } else { CP_WAIT0; }
        __syncthreads();

        #pragma unroll
        for (int kc = 0; kc < 2; kc++) {
            unsigned af[4][4];
            #pragma unroll
            for (int mt = 0; mt < 4; mt++) {
                unsigned a = sA + cur * bufA +
                    ((mBase + mt * 16 + rowOff) * AS_LD + kc * 16 + colOff) * 2;
                ldsm4(a, af[mt][0], af[mt][1], af[mt][2], af[mt][3]);
            }
            unsigned bf[4][2];
            #pragma unroll
            for (int np = 0; np < 2; np++) {
                unsigned a = sB + cur * bufB +
                    ((kc * 16 + rowOff) * BS_LD + nBase + np * 16 + colOff) * 2;
                unsigned r0, r1, r2, r3;
                ldsm4t(a, r0, r1, r2, r3);
                bf[2 * np][0] = r0;     bf[2 * np][1] = r1;
                bf[2 * np + 1][0] = r2; bf[2 * np + 1][1] = r3;
            }
            #pragma unroll
            for (int mt = 0; mt < 4; mt++)
                #pragma unroll
                for (int nt = 0; nt < 4; nt++)
                    mma16816(acc[mt][nt], af[mt], bf[nt][0], bf[nt][1]);
        }
        __syncthreads();
    }

    #pragma unroll
    for (int mt = 0; mt < 4; mt++)
        #pragma unroll
        for (int hh = 0; hh < 2; hh++) {
            size_t row = (size_t)by * 128 + mBase + mt * 16 + g + hh * 8;
            #pragma unroll
            for (int nt = 0; nt < 4; nt++) {
                int col = bx * 128 + nBase + nt * 8 + 2 * qd;
                float ox = acc[mt][nt][hh * 2 + 0] + bias[col];
                float oy = acc[mt][nt][hh * 2 + 1] + bias[col + 1];
                if (HALF_OUT) {
                    *reinterpret_cast<__half2*>((__half*)Cout + row * HID + col) =
                        __floats2half2_rn(ox, oy);
                } else {
                    const float2 r = *(const float2*)(addsrc + row * HID + col);
                    *(float2*)((float*)Cout + row * HID + col) =
                        make_float2(ox + r.x, oy + r.y);
                }
            }
        }
}

// ---- RoPE in place (fp16); q pre-scaled by 1/8 ----
__global__ __launch_bounds__(NHEAD * 32) void rope_kernel(
    __half* __restrict__ q, __half* __restrict__ k)
{
    int t = blockIdx.x;
    int h = threadIdx.x >> 5, i = threadIdx.x & 31;
    int pos = t & (SEQL - 1);
    float invf  = powf(10000.0f, -((float)(2 * i) / (float)HDIM));
    float theta = (float)pos * invf;
    float sn, cs; sincosf(theta, &sn, &cs);
    size_t base = (size_t)t * HID + h * HDIM;
    float x1 = __half2float(q[base + i]), x2 = __half2float(q[base + 32 + i]);
    q[base + i]      = __float2half_rn((x1 * cs - x2 * sn) * 0.125f);
    q[base + 32 + i] = __float2half_rn((x2 * cs + x1 * sn) * 0.125f);
    x1 = __half2float(k[base + i]); x2 = __half2float(k[base + 32 + i]);
    k[base + i]      = __float2half_rn(x1 * cs - x2 * sn);
    k[base + 32 + i] = __float2half_rn(x2 * cs + x1 * sn);
}

// ---- Flash attention fp16: Bq=128, Bkv=64, 8 warps, P in registers ----
#define AT_LD 72

__global__ __launch_bounds__(256) void attn_kernel(
    const __half* __restrict__ Q, const __half* __restrict__ Kg,
    const __half* __restrict__ Vg, __half* __restrict__ O)
{
    extern __shared__ __align__(16) __half smh[];
    __half* Qs = smh;
    const int KVB = 2 * 64 * AT_LD;  // halves per (K+V) buffer

    int qt = blockIdx.x, h = blockIdx.y, sq = blockIdx.z;
    int tid = threadIdx.x, w = tid >> 5, lane = tid & 31;
    int g = lane >> 2, qd = lane & 3;
    int rBase = w * 16;
    const size_t seqBase = (size_t)sq * SEQL;
    int i8 = lane & 7, sel = lane >> 3;
    int rowOff = i8 + (sel & 1) * 8;
    int colOff = (sel & 2) ? 8 : 0;

    unsigned sBase = (unsigned)__cvta_generic_to_shared(smh);
    unsigned sQ = sBase;
    unsigned sKV0 = sBase + 128 * AT_LD * 2;

    {   // load Q tile
        int qrow = tid >> 1, qseg = (tid & 1) * 32;
        const uint4* qg = (const uint4*)(Q + (seqBase + (size_t)qt * 128 + qrow) * HID
                                           + h * HDIM + qseg);
        uint4* qs = (uint4*)(Qs + qrow * AT_LD + qseg);
        #pragma unroll
        for (int u = 0; u < 4; u++) qs[u] = qg[u];
    }

    int krow = tid >> 2, kseg = (tid & 3) * 16;
    const __half* kgp = Kg + (seqBase + krow) * HID + h * HDIM + kseg;
    const __half* vgp = Vg + (seqBase + krow) * HID + h * HDIM + kseg;
    unsigned dK = sKV0 + (krow * AT_LD + kseg) * 2;
    unsigned dV = dK + 64 * AT_LD * 2;

    cpa16(dK, kgp); cpa16(dK + 16, kgp + 8);
    cpa16(dV, vgp); cpa16(dV + 16, vgp + 8);
    CP_COMMIT;
    __syncthreads();  // Qs visible

    unsigned qf[4][4];
    #pragma unroll
    for (int kc = 0; kc < 4; kc++) {
        unsigned a = sQ + ((rBase + rowOff) * AT_LD + kc * 16 + colOff) * 2;
        ldsm4(a, qf[kc][0], qf[kc][1], qf[kc][2], qf[kc][3]);
    }

    float oAcc[8][4];
    #pragma unroll
    for (int nt = 0; nt < 8; nt++)
        #pragma unroll
        for (int i = 0; i < 4; i++) oAcc[nt][i] = 0.f;
    float m1 = -1e30f, m2 = -1e30f, l1 = 0.f, l2 = 0.f;

    const int NKT = SEQL / 64;
    for (int kt = 0; kt < NKT; kt++) {
        int cur = kt & 1, nxt = cur ^ 1;
        if (kt + 1 < NKT) {
            size_t off = (size_t)(kt + 1) * 64 * HID;
            unsigned dKn = sKV0 + nxt * KVB * 2 + (krow * AT_LD + kseg) * 2;
            unsigned dVn = dKn + 64 * AT_LD * 2;
            cpa16(dKn, kgp + off); cpa16(dKn + 16, kgp + off + 8);
            cpa16(dVn, vgp + off); cpa16(dVn + 16, vgp + off + 8);
            CP_COMMIT; CP_WAIT1;
        } else { CP_WAIT0; }
        __syncthreads();

        unsigned sK = sKV0 + cur * KVB * 2;
        unsigned sV = sK + 64 * AT_LD * 2;

        // S = Q K^T
        float sAcc[8][4];
        #pragma unroll
        for (int nt = 0; nt < 8; nt++) {
            #pragma unroll
            for (int i = 0; i < 4; i++) sAcc[nt][i] = 0.f;
            unsigned r0, r1, r2, r3;
            unsigned a0 = sK + ((nt * 8 + i8) * AT_LD + sel * 8) * 2;
            ldsm4(a0, r0, r1, r2, r3);
            mma16816(sAcc[nt], qf[0], r0, r1);
            mma16816(sAcc[nt], qf[1], r2, r3);
            unsigned a1 = sK + ((nt * 8 + i8) * AT_LD + 32 + sel * 8) * 2;
            ldsm4(a1, r0, r1, r2, r3);
            mma16816(sAcc[nt], qf[2], r0, r1);
            mma16816(sAcc[nt], qf[3], r2, r3);
        }

        // online softmax (rows rBase+g, rBase+g+8)
        float rmax1 = -1e30f, rmax2 = -1e30f;
        #pragma unroll
        for (int nt = 0; nt < 8; nt++) {
            rmax1 = fmaxf(rmax1, fmaxf(sAcc[nt][0], sAcc[nt][1]));
            rmax2 = fmaxf(rmax2, fmaxf(sAcc[nt][2], sAcc[nt][3]));
        }
        rmax1 = fmaxf(rmax1, __shfl_xor_sync(0xffffffffu, rmax1, 1));
        rmax1 = fmaxf(rmax1, __shfl_xor_sync(0xffffffffu, rmax1, 2));
        rmax2 = fmaxf(rmax2, __shfl_xor_sync(0xffffffffu, rmax2, 1));
        rmax2 = fmaxf(rmax2, __shfl_xor_sync(0xffffffffu, rmax2, 2));
        float mn1 = fmaxf(m1, rmax1), mn2 = fmaxf(m2, rmax2);
        float alpha1 = __expf(m1 - mn1), alpha2 = __expf(m2 - mn2);
        m1 = mn1; m2 = mn2;
        float rs1 = 0.f, rs2 = 0.f;
        #pragma unroll
        for (int nt = 0; nt < 8; nt++) {
            sAcc[nt][0] = __expf(sAcc[nt][0] - m1);
            sAcc[nt][1] = __expf(sAcc[nt][1] - m1);
            sAcc[nt][2] = __expf(sAcc[nt][2] - m2);
            sAcc[nt][3] = __expf(sAcc[nt][3] - m2);
            rs1 += sAcc[nt][0] + sAcc[nt][1];
            rs2 += sAcc[nt][2] + sAcc[nt][3];
        }
        rs1 += __shfl_xor_sync(0xffffffffu, rs1, 1);
        rs1 += __shfl_xor_sync(0xffffffffu, rs1, 2);
        rs2 += __shfl_xor_sync(0xffffffffu, rs2, 1);
        rs2 += __shfl_xor_sync(0xffffffffu, rs2, 2);
        l1 = l1 * alpha1 + rs1;
        l2 = l2 * alpha2 + rs2;
        #pragma unroll
        for (int nt = 0; nt < 8; nt++) {
            oAcc[nt][0] *= alpha1; oAcc[nt][1] *= alpha1;
            oAcc[nt][2] *= alpha2; oAcc[nt][3] *= alpha2;
        }

        // O += P V (P packed in-register)
        #pragma unroll
        for (int kc = 0; kc < 4; kc++) {
            unsigned pf[4];
            pf[0] = f22h(sAcc[2 * kc][0], sAcc[2 * kc][1]);
            pf[1] = f22h(sAcc[2 * kc][2], sAcc[2 * kc][3]);
            pf[2] = f22h(sAcc[2 * kc + 1][0], sAcc[2 * kc + 1][1]);
            pf[3] = f22h(sAcc[2 * kc + 1][2], sAcc[2 * kc + 1][3]);
            #pragma unroll
            for (int np = 0; np < 4; np++) {
                unsigned r0, r1, r2, r3;
                unsigned a = sV + ((kc * 16 + rowOff) * AT_LD + np * 16 + colOff) * 2;
                ldsm4t(a, r0, r1, r2, r3);
                mma16816(oAcc[2 * np],     pf, r0, r1);
                mma16816(oAcc[2 * np + 1], pf, r2, r3);
            }
        }
        __syncthreads();
    }

    float inv1 = 1.0f / l1, inv2 = 1.0f / l2;
    size_t row1 = seqBase + (size_t)qt * 128 + rBase + g;
    size_t row2 = row1 + 8;
    #pragma unroll
    for (int nt = 0; nt < 8; nt++) {
        int col = h * HDIM + nt * 8 + 2 * qd;
        *reinterpret_cast<__half2*>(O + row1 * HID + col) =
            __floats2half2_rn(oAcc[nt][0] * inv1, oAcc[nt][1] * inv1);
        *reinterpret_cast<__half2*>(O + row2 * HID + col) =
            __floats2half2_rn(oAcc[nt][2] * inv2, oAcc[nt][3] * inv2);
    }
}

// ---------------------------------------------------------------------------
extern "C" void kernel_launch(void* const* d_in, const int* in_sizes, int n_in,
                              void* d_out, int out_size)
{
    (void)in_sizes; (void)n_in; (void)out_size;
    const float* hs = (const float*)d_in[0];
    const float* nw = (const float*)d_in[3];
    const float* nb = (const float*)d_in[4];
    const float* Wq = (const float*)d_in[5];
    const float* bq = (const float*)d_in[6];
    const float* Wk = (const float*)d_in[7];
    const float* bk = (const float*)d_in[8];
    const float* Wv = (const float*)d_in[9];
    const float* bv = (const float*)d_in[10];
    const float* Wo = (const float*)d_in[11];
    const float* bo = (const float*)d_in[12];
    float* out = (float*)d_out;

    float* xn; __half *xh, *q, *k, *v, *att, *Wh;
    cudaGetSymbolAddress((void**)&xn,  g_xn);
    cudaGetSymbolAddress((void**)&xh,  g_xh);
    cudaGetSymbolAddress((void**)&q,   g_q);
    cudaGetSymbolAddress((void**)&k,   g_k);
    cudaGetSymbolAddress((void**)&v,   g_v);
    cudaGetSymbolAddress((void**)&att, g_att);
    cudaGetSymbolAddress((void**)&Wh,  g_Wh);

    const int ATTN_SMEM = (128 * AT_LD + 2 * 2 * 64 * AT_LD) * (int)sizeof(__half);
    static int attr_done = 0;
    if (!attr_done) {
        cudaFuncSetAttribute(attn_kernel,
                             cudaFuncAttributeMaxDynamicSharedMemorySize, ATTN_SMEM);
        attr_done = 1;
    }

    w2h_kernel<<<HID * HID / 256, 256>>>(Wq, Wk, Wv, Wo);
    ln_kernel<<<TTOK, 256>>>(hs, nw, nb, xn, xh);

    dim3 ggrid(HID / 128, TTOK / 128);
    gemm_kernel<true><<<ggrid, 256>>>(xh, Wh + 0 * HID * HID, bq, nullptr, q);
    gemm_kernel<true><<<ggrid, 256>>>(xh, Wh + 1 * HID * HID, bk, nullptr, k);
    gemm_kernel<true><<<ggrid, 256>>>(xh, Wh + 2 * HID * HID, bv, nullptr, v);

    rope_kernel<<<TTOK, NHEAD * 32>>>(q, k);

    dim3 agrid(SEQL / 128, NHEAD, NSEQ);
    attn_kernel<<<agrid, 256, ATTN_SMEM>>>(q, k, v, att);

    gemm_kernel<false><<<ggrid, 256>>>(att, Wh + 3 * HID * HID, bo, xn, out);
}

// round 12
// speedup vs baseline: 3.5943x; 1.1225x over previous
#include <cuda_runtime.h>
#include <cuda_fp16.h>
#include <stdint.h>
#include <cstdint>
#include <math.h>

#define TTOK  16384
#define HID   768
#define NHEAD 12
#define HDIM  64
#define SEQL  2048
#define NSEQ  8

__device__ float  g_xn [TTOK * HID];
__device__ __half g_xh [TTOK * HID];
__device__ __half g_q  [TTOK * HID];
__device__ __half g_k  [TTOK * HID];
__device__ __half g_v  [TTOK * HID];
__device__ __half g_att[TTOK * HID];
__device__ __half g_Wh [4][HID * HID];

__device__ __forceinline__ void ldsm4(unsigned a, unsigned &r0, unsigned &r1,
                                      unsigned &r2, unsigned &r3) {
    asm volatile("ldmatrix.sync.aligned.m8n8.x4.shared.b16 {%0,%1,%2,%3}, [%4];"
        : "=r"(r0), "=r"(r1), "=r"(r2), "=r"(r3) : "r"(a));
}
__device__ __forceinline__ void ldsm4t(unsigned a, unsigned &r0, unsigned &r1,
                                       unsigned &r2, unsigned &r3) {
    asm volatile("ldmatrix.sync.aligned.m8n8.x4.trans.shared.b16 {%0,%1,%2,%3}, [%4];"
        : "=r"(r0), "=r"(r1), "=r"(r2), "=r"(r3) : "r"(a));
}
__device__ __forceinline__ void mma16816(float* c, const unsigned* a,
                                         unsigned b0, unsigned b1) {
    asm volatile(
        "mma.sync.aligned.m16n8k16.row.col.f32.f16.f16.f32 "
        "{%0,%1,%2,%3},{%4,%5,%6,%7},{%8,%9},{%0,%1,%2,%3};"
        : "+f"(c[0]), "+f"(c[1]), "+f"(c[2]), "+f"(c[3])
        : "r"(a[0]), "r"(a[1]), "r"(a[2]), "r"(a[3]), "r"(b0), "r"(b1));
}
__device__ __forceinline__ void cpa16(unsigned d, const void* s) {
    asm volatile("cp.async.ca.shared.global [%0], [%1], 16;" :: "r"(d), "l"(s));
}
#define CP_COMMIT  asm volatile("cp.async.commit_group;")
#define CP_WAIT0   asm volatile("cp.async.wait_group 0;")
#define CP_WAIT1   asm volatile("cp.async.wait_group 1;")

__device__ __forceinline__ unsigned f22h(float x, float y) {
    __half2 h = __floats2half2_rn(x, y);
    return *reinterpret_cast<unsigned*>(&h);
}
__device__ __forceinline__ float ex2(float x) {
    float r; asm("ex2.approx.f32 %0, %1;" : "=f"(r) : "f"(x)); return r;
}

// softmax scale folded with log2(e): scores come out in log2 domain
#define QSCALE 0.1803368801111843f   // 0.125 * log2(e)

// ---- weight fp32->fp16, once ----
__global__ __launch_bounds__(256) void w2h_kernel(
    const float* __restrict__ a, const float* __restrict__ b,
    const float* __restrict__ c, const float* __restrict__ d)
{
    int i = blockIdx.x * 256 + threadIdx.x;
    g_Wh[0][i] = __float2half_rn(a[i]);
    g_Wh[1][i] = __float2half_rn(b[i]);
    g_Wh[2][i] = __float2half_rn(c[i]);
    g_Wh[3][i] = __float2half_rn(d[i]);
}

// ---- LayerNorm: fp32 out (residual) + fp16 out (GEMM A) ----
__global__ __launch_bounds__(256) void ln_kernel(
    const float* __restrict__ x, const float* __restrict__ w,
    const float* __restrict__ b, float* __restrict__ xn, __half* __restrict__ xh)
{
    int row = blockIdx.x, tid = threadIdx.x;
    const float* xr = x + (size_t)row * HID;
    float v0 = xr[tid], v1 = xr[tid + 256], v2 = xr[tid + 512];
    float s = v0 + v1 + v2, ss = v0 * v0 + v1 * v1 + v2 * v2;
    #pragma unroll
    for (int o = 16; o > 0; o >>= 1) {
        s  += __shfl_xor_sync(0xffffffffu, s,  o);
        ss += __shfl_xor_sync(0xffffffffu, ss, o);
    }
    __shared__ float sm[8], sm2[8];
    if ((tid & 31) == 0) { sm[tid >> 5] = s; sm2[tid >> 5] = ss; }
    __syncthreads();
    float ts = 0.f, tss = 0.f;
    #pragma unroll
    for (int i = 0; i < 8; i++) { ts += sm[i]; tss += sm2[i]; }
    float mean = ts * (1.0f / HID);
    float var  = tss * (1.0f / HID) - mean * mean;
    float inv  = rsqrtf(var + 1e-12f);
    float* xo = xn + (size_t)row * HID;
    __half* xo2 = xh + (size_t)row * HID;
    float o0 = (v0 - mean) * inv * w[tid      ] + b[tid      ];
    float o1 = (v1 - mean) * inv * w[tid + 256] + b[tid + 256];
    float o2 = (v2 - mean) * inv * w[tid + 512] + b[tid + 512];
    xo[tid] = o0; xo[tid + 256] = o1; xo[tid + 512] = o2;
    xo2[tid] = __float2half_rn(o0);
    xo2[tid + 256] = __float2half_rn(o1);
    xo2[tid + 512] = __float2half_rn(o2);
}

// ---- fp16 GEMM body: 128x128 tile, BK=32, 8 warps, 3-stage cp.async ----
#define AS_LD 40
#define BS_LD 136
#define GSTG  3

template<bool HALF_OUT>
__device__ __forceinline__ void gemm_body(
    const __half* __restrict__ A, const __half* __restrict__ B,
    const float* __restrict__ bias, const float* __restrict__ addsrc,
    __half* __restrict__ outH, float* __restrict__ outF)
{
    extern __shared__ __align__(16) __half gsm[];

    int bx = blockIdx.x, by = blockIdx.y;
    int tid = threadIdx.x, w = tid >> 5, lane = tid & 31;
    int g = lane >> 2, qd = lane & 3;
    int mBase = (w >> 2) * 64, nBase = (w & 3) * 32;
    int i8 = lane & 7, sel = lane >> 3;
    int rowOff = i8 + (sel & 1) * 8;
    int colOff = (sel & 2) ? 8 : 0;

    int aRow = tid >> 1, aSeg = (tid & 1) * 16;
    int bK = tid >> 3, bSeg = (tid & 7) * 16;
    const __half* aG = A + (size_t)(by * 128 + aRow) * HID + aSeg;
    const __half* bG = B + (size_t)bK * HID + bx * 128 + bSeg;

    unsigned sA = (unsigned)__cvta_generic_to_shared(gsm);
    unsigned sB = sA + GSTG * 128 * AS_LD * 2;
    const unsigned bufA = 128 * AS_LD * 2, bufB = 32 * BS_LD * 2;
    unsigned dA = sA + (aRow * AS_LD + aSeg) * 2;
    unsigned dB = sB + (bK * BS_LD + bSeg) * 2;

    float acc[4][4][4];
    #pragma unroll
    for (int mt = 0; mt < 4; mt++)
        #pragma unroll
        for (int nt = 0; nt < 4; nt++)
            #pragma unroll
            for (int i = 0; i < 4; i++) acc[mt][nt][i] = 0.f;

    // prologue: stages 0,1
    #pragma unroll
    for (int s = 0; s < 2; s++) {
        int k0 = s * 32;
        cpa16(dA + s * bufA, aG + k0);
        cpa16(dA + s * bufA + 16, aG + k0 + 8);
        cpa16(dB + s * bufB, bG + (size_t)k0 * HID);
        cpa16(dB + s * bufB + 16, bG + (size_t)k0 * HID + 8);
        CP_COMMIT;
    }

    const int NI = HID / 32;  // 24
    int stage = 0, pst = 2;
    for (int c = 0; c < NI; c++) {
        CP_WAIT1;
        __syncthreads();
        // prefetch chunk c+2 into stage (c+2)%3 == (c-1)%3 — all warps have
        // finished compute of c-1 (they passed this barrier), so it's free.
        if (c + 2 < NI) {
            int k0 = (c + 2) * 32;
            cpa16(dA + pst * bufA, aG + k0);
            cpa16(dA + pst * bufA + 16, aG + k0 + 8);
            cpa16(dB + pst * bufB, bG + (size_t)k0 * HID);
            cpa16(dB + pst * bufB + 16, bG + (size_t)k0 * HID + 8);
        }
        CP_COMMIT;

        unsigned cA = sA + stage * bufA;
        unsigned cB = sB + stage * bufB;
        #pragma unroll
        for (int kc = 0; kc < 2; kc++) {
            unsigned af[4][4];
            #pragma unroll
            for (int mt = 0; mt < 4; mt++) {
                unsigned a = cA +
                    ((mBase + mt * 16 + rowOff) * AS_LD + kc * 16 + colOff) * 2;
                ldsm4(a, af[mt][0], af[mt][1], af[mt][2], af[mt][3]);
            }
            unsigned bf[4][2];
            #pragma unroll
            for (int np = 0; np < 2; np++) {
                unsigned a = cB +
                    ((kc * 16 + rowOff) * BS_LD + nBase + np * 16 + colOff) * 2;
                unsigned r0, r1, r2, r3;
                ldsm4t(a, r0, r1, r2, r3);
                bf[2 * np][0] = r0;     bf[2 * np][1] = r1;
                bf[2 * np + 1][0] = r2; bf[2 * np + 1][1] = r3;
            }
            #pragma unroll
            for (int mt = 0; mt < 4; mt++)
                #pragma unroll
                for (int nt = 0; nt < 4; nt++)
                    mma16816(acc[mt][nt], af[mt], bf[nt][0], bf[nt][1]);
        }
        stage = (stage + 1 == GSTG) ? 0 : stage + 1;
        pst   = (pst   + 1 == GSTG) ? 0 : pst + 1;
    }

    #pragma unroll
    for (int mt = 0; mt < 4; mt++)
        #pragma unroll
        for (int hh = 0; hh < 2; hh++) {
            size_t row = (size_t)by * 128 + mBase + mt * 16 + g + hh * 8;
            #pragma unroll
            for (int nt = 0; nt < 4; nt++) {
                int col = bx * 128 + nBase + nt * 8 + 2 * qd;
                float ox = acc[mt][nt][hh * 2 + 0] + bias[col];
                float oy = acc[mt][nt][hh * 2 + 1] + bias[col + 1];
                if (HALF_OUT) {
                    *reinterpret_cast<__half2*>(outH + row * HID + col) =
                        __floats2half2_rn(ox, oy);
                } else {
                    const float2 r = *(const float2*)(addsrc + row * HID + col);
                    *(float2*)(outF + row * HID + col) =
                        make_float2(ox + r.x, oy + r.y);
                }
            }
        }
}

// Fused Q/K/V projection: blockIdx.z selects weight/bias/output
__global__ __launch_bounds__(256) void qkv_kernel(
    const __half* __restrict__ xh,
    const float* __restrict__ bq, const float* __restrict__ bk,
    const float* __restrict__ bv)
{
    int z = blockIdx.z;
    const float* bias = (z == 0) ? bq : (z == 1) ? bk : bv;
    __half* out = (z == 0) ? g_q : (z == 1) ? g_k : g_v;
    gemm_body<true>(xh, g_Wh[z], bias, nullptr, out, nullptr);
}

__global__ __launch_bounds__(256) void ogemm_kernel(
    const float* __restrict__ bo, float* __restrict__ out)
{
    gemm_body<false>(g_att, g_Wh[3], bo, g_xn, nullptr, out);
}

// ---- RoPE in place (fp16); q pre-scaled by QSCALE (1/8 * log2e) ----
__global__ __launch_bounds__(NHEAD * 32) void rope_kernel(
    __half* __restrict__ q, __half* __restrict__ k)
{
    int t = blockIdx.x;
    int h = threadIdx.x >> 5, i = threadIdx.x & 31;
    int pos = t & (SEQL - 1);
    float invf  = powf(10000.0f, -((float)(2 * i) / (float)HDIM));
    float theta = (float)pos * invf;
    float sn, cs; sincosf(theta, &sn, &cs);
    size_t base = (size_t)t * HID + h * HDIM;
    float x1 = __half2float(q[base + i]), x2 = __half2float(q[base + 32 + i]);
    q[base + i]      = __float2half_rn((x1 * cs - x2 * sn) * QSCALE);
    q[base + 32 + i] = __float2half_rn((x2 * cs + x1 * sn) * QSCALE);
    x1 = __half2float(k[base + i]); x2 = __half2float(k[base + 32 + i]);
    k[base + i]      = __float2half_rn(x1 * cs - x2 * sn);
    k[base + 32 + i] = __float2half_rn(x2 * cs + x1 * sn);
}

// ---- Flash attention fp16: Bq=128, Bkv=64, 8 warps, 3-stage KV pipeline ----
#define AT_LD 72

__global__ __launch_bounds__(256) void attn_kernel(
    const __half* __restrict__ Q, const __half* __restrict__ Kg,
    const __half* __restrict__ Vg, __half* __restrict__ O)
{
    extern __shared__ __align__(16) __half smh[];
    __half* Qs = smh;
    const int KVB = 2 * 64 * AT_LD;  // halves per (K+V) stage

    int qt = blockIdx.x, h = blockIdx.y, sq = blockIdx.z;
    int tid = threadIdx.x, w = tid >> 5, lane = tid & 31;
    int g = lane >> 2, qd = lane & 3;
    int rBase = w * 16;
    const size_t seqBase = (size_t)sq * SEQL;
    int i8 = lane & 7, sel = lane >> 3;
    int rowOff = i8 + (sel & 1) * 8;
    int colOff = (sel & 2) ? 8 : 0;

    unsigned sBase = (unsigned)__cvta_generic_to_shared(smh);
    unsigned sQ = sBase;
    unsigned sKV0 = sBase + 128 * AT_LD * 2;

    {   // load Q tile
        int qrow = tid >> 1, qseg = (tid & 1) * 32;
        const uint4* qg = (const uint4*)(Q + (seqBase + (size_t)qt * 128 + qrow) * HID
                                           + h * HDIM + qseg);
        uint4* qs = (uint4*)(Qs + qrow * AT_LD + qseg);
        #pragma unroll
        for (int u = 0; u < 4; u++) qs[u] = qg[u];
    }

    int krow = tid >> 2, kseg = (tid & 3) * 16;
    const __half* kgp = Kg + (seqBase + krow) * HID + h * HDIM + kseg;
    const __half* vgp = Vg + (seqBase + krow) * HID + h * HDIM + kseg;
    unsigned dK = sKV0 + (krow * AT_LD + kseg) * 2;
    unsigned dV = dK + 64 * AT_LD * 2;

    // prologue: KV tiles 0,1 into stages 0,1
    #pragma unroll
    for (int s = 0; s < 2; s++) {
        size_t off = (size_t)s * 64 * HID;
        cpa16(dK + s * KVB * 2, kgp + off);
        cpa16(dK + s * KVB * 2 + 16, kgp + off + 8);
        cpa16(dV + s * KVB * 2, vgp + off);
        cpa16(dV + s * KVB * 2 + 16, vgp + off + 8);
        CP_COMMIT;
    }
    __syncthreads();  // Qs visible

    unsigned qf[4][4];
    #pragma unroll
    for (int kc = 0; kc < 4; kc++) {
        unsigned a = sQ + ((rBase + rowOff) * AT_LD + kc * 16 + colOff) * 2;
        ldsm4(a, qf[kc][0], qf[kc][1], qf[kc][2], qf[kc][3]);
    }

    float oAcc[8][4];
    #pragma unroll
    for (int nt = 0; nt < 8; nt++)
        #pragma unroll
        for (int i = 0; i < 4; i++) oAcc[nt][i] = 0.f;
    float m1 = -1e30f, m2 = -1e30f, l1 = 0.f, l2 = 0.f;

    const int NKT = SEQL / 64;  // 32
    int stage = 0, pst = 2;
    for (int kt = 0; kt < NKT; kt++) {
        CP_WAIT1;
        __syncthreads();
        // prefetch tile kt+2 into stage (kt-1)%3 — freed by the barrier above
        if (kt + 2 < NKT) {
            size_t off = (size_t)(kt + 2) * 64 * HID;
            unsigned dKn = dK + pst * KVB * 2;
            unsigned dVn = dV + pst * KVB * 2;
            cpa16(dKn, kgp + off); cpa16(dKn + 16, kgp + off + 8);
            cpa16(dVn, vgp + off); cpa16(dVn + 16, vgp + off + 8);
        }
        CP_COMMIT;

        unsigned sK = sKV0 + stage * KVB * 2;
        unsigned sV = sK + 64 * AT_LD * 2;

        // S = Q K^T (log2 domain: Q pre-scaled by 1/8*log2e)
        float sAcc[8][4];
        #pragma unroll
        for (int nt = 0; nt < 8; nt++) {
            #pragma unroll
            for (int i = 0; i < 4; i++) sAcc[nt][i] = 0.f;
            unsigned r0, r1, r2, r3;
            unsigned a0 = sK + ((nt * 8 + i8) * AT_LD + sel * 8) * 2;
            ldsm4(a0, r0, r1, r2, r3);
            mma16816(sAcc[nt], qf[0], r0, r1);
            mma16816(sAcc[nt], qf[1], r2, r3);
            unsigned a1 = sK + ((nt * 8 + i8) * AT_LD + 32 + sel * 8) * 2;
            ldsm4(a1, r0, r1, r2, r3);
            mma16816(sAcc[nt], qf[2], r0, r1);
            mma16816(sAcc[nt], qf[3], r2, r3);
        }

        // online softmax in exp2 domain (rows rBase+g, rBase+g+8)
        float rmax1 = -1e30f, rmax2 = -1e30f;
        #pragma unroll
        for (int nt = 0; nt < 8; nt++) {
            rmax1 = fmaxf(rmax1, fmaxf(sAcc[nt][0], sAcc[nt][1]));
            rmax2 = fmaxf(rmax2, fmaxf(sAcc[nt][2], sAcc[nt][3]));
        }
        rmax1 = fmaxf(rmax1, __shfl_xor_sync(0xffffffffu, rmax1, 1));
        rmax1 = fmaxf(rmax1, __shfl_xor_sync(0xffffffffu, rmax1, 2));
        rmax2 = fmaxf(rmax2, __shfl_xor_sync(0xffffffffu, rmax2, 1));
        rmax2 = fmaxf(rmax2, __shfl_xor_sync(0xffffffffu, rmax2, 2));
        float mn1 = fmaxf(m1, rmax1), mn2 = fmaxf(m2, rmax2);
        float alpha1 = ex2(m1 - mn1), alpha2 = ex2(m2 - mn2);
        m1 = mn1; m2 = mn2;
        float rs1 = 0.f, rs2 = 0.f;
        #pragma unroll
        for (int nt = 0; nt < 8; nt++) {
            sAcc[nt][0] = ex2(sAcc[nt][0] - m1);
            sAcc[nt][1] = ex2(sAcc[nt][1] - m1);
            sAcc[nt][2] = ex2(sAcc[nt][2] - m2);
            sAcc[nt][3] = ex2(sAcc[nt][3] - m2);
            rs1 += sAcc[nt][0] + sAcc[nt][1];
            rs2 += sAcc[nt][2] + sAcc[nt][3];
        }
        rs1 += __shfl_xor_sync(0xffffffffu, rs1, 1);
        rs1 += __shfl_xor_sync(0xffffffffu, rs1, 2);
        rs2 += __shfl_xor_sync(0xffffffffu, rs2, 1);
        rs2 += __shfl_xor_sync(0xffffffffu, rs2, 2);
        l1 = l1 * alpha1 + rs1;
        l2 = l2 * alpha2 + rs2;
        #pragma unroll
        for (int nt = 0; nt < 8; nt++) {
            oAcc[nt][0] *= alpha1; oAcc[nt][1] *= alpha1;
            oAcc[nt][2] *= alpha2; oAcc[nt][3] *= alpha2;
        }

        // O += P V (P packed in-register)
        #pragma unroll
        for (int kc = 0; kc < 4; kc++) {
            unsigned pf[4];
            pf[0] = f22h(sAcc[2 * kc][0], sAcc[2 * kc][1]);
            pf[1] = f22h(sAcc[2 * kc][2], sAcc[2 * kc][3]);
            pf[2] = f22h(sAcc[2 * kc + 1][0], sAcc[2 * kc + 1][1]);
            pf[3] = f22h(sAcc[2 * kc + 1][2], sAcc[2 * kc + 1][3]);
            #pragma unroll
            for (int np = 0; np < 4; np++) {
                unsigned r0, r1, r2, r3;
                unsigned a = sV + ((kc * 16 + rowOff) * AT_LD + np * 16 + colOff) * 2;
                ldsm4t(a, r0, r1, r2, r3);
                mma16816(oAcc[2 * np],     pf, r0, r1);
                mma16816(oAcc[2 * np + 1], pf, r2, r3);
            }
        }
        stage = (stage + 1 == 3) ? 0 : stage + 1;
        pst   = (pst   + 1 == 3) ? 0 : pst + 1;
    }

    float inv1 = 1.0f / l1, inv2 = 1.0f / l2;
    size_t row1 = seqBase + (size_t)qt * 128 + rBase + g;
    size_t row2 = row1 + 8;
    #pragma unroll
    for (int nt = 0; nt < 8; nt++) {
        int col = h * HDIM + nt * 8 + 2 * qd;
        *reinterpret_cast<__half2*>(O + row1 * HID + col) =
            __floats2half2_rn(oAcc[nt][0] * inv1, oAcc[nt][1] * inv1);
        *reinterpret_cast<__half2*>(O + row2 * HID + col) =
            __floats2half2_rn(oAcc[nt][2] * inv2, oAcc[nt][3] * inv2);
    }
}

// ---------------------------------------------------------------------------
extern "C" void kernel_launch(void* const* d_in, const int* in_sizes, int n_in,
                              void* d_out, int out_size)
{
    (void)in_sizes; (void)n_in; (void)out_size;
    const float* hs = (const float*)d_in[0];
    const float* nw = (const float*)d_in[3];
    const float* nb = (const float*)d_in[4];
    const float* Wq = (const float*)d_in[5];
    const float* bq = (const float*)d_in[6];
    const float* Wk = (const float*)d_in[7];
    const float* bk = (const float*)d_in[8];
    const float* Wv = (const float*)d_in[9];
    const float* bv = (const float*)d_in[10];
    const float* Wo = (const float*)d_in[11];
    const float* bo = (const float*)d_in[12];
    float* out = (float*)d_out;

    float* xn; __half *xh, *q, *k, *v, *att;
    cudaGetSymbolAddress((void**)&xn,  g_xn);
    cudaGetSymbolAddress((void**)&xh,  g_xh);
    cudaGetSymbolAddress((void**)&q,   g_q);
    cudaGetSymbolAddress((void**)&k,   g_k);
    cudaGetSymbolAddress((void**)&v,   g_v);
    cudaGetSymbolAddress((void**)&att, g_att);

    const int GEMM_SMEM = (GSTG * 128 * AS_LD + GSTG * 32 * BS_LD) * (int)sizeof(__half);
    const int ATTN_SMEM = (128 * AT_LD + 3 * 2 * 64 * AT_LD) * (int)sizeof(__half);
    static int attr_done = 0;
    if (!attr_done) {
        cudaFuncSetAttribute(qkv_kernel,
                             cudaFuncAttributeMaxDynamicSharedMemorySize, GEMM_SMEM);
        cudaFuncSetAttribute(ogemm_kernel,
                             cudaFuncAttributeMaxDynamicSharedMemorySize, GEMM_SMEM);
        cudaFuncSetAttribute(attn_kernel,
                             cudaFuncAttributeMaxDynamicSharedMemorySize, ATTN_SMEM);
        attr_done = 1;
    }

    w2h_kernel<<<HID * HID / 256, 256>>>(Wq, Wk, Wv, Wo);
    ln_kernel<<<TTOK, 256>>>(hs, nw, nb, xn, xh);

    dim3 qkvgrid(HID / 128, TTOK / 128, 3);
    qkv_kernel<<<qkvgrid, 256, GEMM_SMEM>>>(xh, bq, bk, bv);

    rope_kernel<<<TTOK, NHEAD * 32>>>(q, k);

    dim3 agrid(SEQL / 128, NHEAD, NSEQ);
    attn_kernel<<<agrid, 256, ATTN_SMEM>>>(q, k, v, att);

    dim3 ogrid(HID / 128, TTOK / 128);
    ogemm_kernel<<<ogrid, 256, GEMM_SMEM>>>(bo, out);
}